// round 1
// baseline (speedup 1.0000x reference)
#include <cuda_runtime.h>

#define NTOK 32768          // B*T = 16*2048
#define INCH 512
#define DLAT 256
#define ZW   768            // 3*DLAT
#define VC   1024
#define VP   1024
#define VT   512

// output layout: x_recon | vq_loss | idx_c | idx_p | idx_t | zq_c | zq_p | zq_t
#define LOSS_OFF (NTOK*INCH)            // 16777216
#define IDX_OFF  (LOSS_OFF + 1)         // 16777217
#define ZQ_OFF   (IDX_OFF + 3*NTOK)     // 16875521

// -------- scratch (device globals: allocation-free kernel_launch) --------
__device__ float  g_z[NTOK*ZW];         // z = x@W+b, heads interleaved per row
__device__ float  g_zq[NTOK*ZW];        // straight-through zq, aligned for recon GEMM
__device__ float  g_zz[3*NTOK];         // per (head,token) sum z^2
__device__ float  g_cc[VC+VP+VT];       // per codebook-row sum cb^2
__device__ float2 g_part[3*NTOK*8];     // per (head,token,vtile) (best score, idx bits)
__device__ float  g_losspart[3*512];    // per (head, token-block) loss partial

// ============================================================
// Kernel 1: z[m, 768] = x[m,512] @ [Wc|Wp|Wt] + [bc|bp|bt]
// 128x128 tile, BK=8, 256 threads, 8x8 per thread
// ============================================================
__global__ __launch_bounds__(256, 2) void gemm_z_kernel(
    const float* __restrict__ x,
    const float* __restrict__ Wc, const float* __restrict__ Wp, const float* __restrict__ Wt,
    const float* __restrict__ bc, const float* __restrict__ bp, const float* __restrict__ bt)
{
    const int nt  = blockIdx.x;                 // 0..5 (column tile of 128 in the 768-wide z)
    const int seg = nt >> 1;                    // head
    const float* W  = (seg == 0) ? Wc : (seg == 1 ? Wp : Wt);
    const float* bb = (seg == 0) ? bc : (seg == 1 ? bp : bt);
    const int nseg = (nt & 1) * 128;            // column offset within head
    const int m0   = blockIdx.y * 128;

    __shared__ float As[8][128];
    __shared__ float Bs[8][128];

    const int tid = threadIdx.x;
    const int tx = tid & 15, ty = tid >> 4;

    float acc[8][8];
    #pragma unroll
    for (int i = 0; i < 8; i++)
        #pragma unroll
        for (int j = 0; j < 8; j++) acc[i][j] = 0.f;

    const int arow = tid >> 1;
    const int akq  = (tid & 1) * 4;
    const int bk   = tid >> 5;
    const int bn   = (tid & 31) * 4;

    const float* aptr = x + (m0 + arow) * INCH + akq;
    const float* bptr = W + bk * DLAT + nseg + bn;

    for (int k0 = 0; k0 < INCH; k0 += 8) {
        float4 av = *(const float4*)(aptr + k0);
        float4 bv = *(const float4*)(bptr + (size_t)k0 * DLAT);
        __syncthreads();
        As[akq+0][arow] = av.x; As[akq+1][arow] = av.y;
        As[akq+2][arow] = av.z; As[akq+3][arow] = av.w;
        *(float4*)&Bs[bk][bn] = bv;
        __syncthreads();
        #pragma unroll
        for (int kk = 0; kk < 8; kk++) {
            float a[8], b[8];
            *(float4*)&a[0] = *(const float4*)&As[kk][ty*8];
            *(float4*)&a[4] = *(const float4*)&As[kk][ty*8+4];
            *(float4*)&b[0] = *(const float4*)&Bs[kk][tx*8];
            *(float4*)&b[4] = *(const float4*)&Bs[kk][tx*8+4];
            #pragma unroll
            for (int i = 0; i < 8; i++)
                #pragma unroll
                for (int j = 0; j < 8; j++)
                    acc[i][j] = fmaf(a[i], b[j], acc[i][j]);
        }
    }

    float bj[8];
    #pragma unroll
    for (int j = 0; j < 8; j++) bj[j] = bb[nseg + tx*8 + j];

    #pragma unroll
    for (int i = 0; i < 8; i++) {
        float* zrow = g_z + (size_t)(m0 + ty*8 + i) * ZW + nt * 128 + tx*8;
        #pragma unroll
        for (int j = 0; j < 8; j += 4) {
            float4 v;
            v.x = acc[i][j+0] + bj[j+0];
            v.y = acc[i][j+1] + bj[j+1];
            v.z = acc[i][j+2] + bj[j+2];
            v.w = acc[i][j+3] + bj[j+3];
            *(float4*)&zrow[j] = v;
        }
    }
}

// ============================================================
// Kernel 2: zz[h*NTOK+tok] = sum_k z[tok, h*256+k]^2 (warp per row)
// ============================================================
__global__ void zz_kernel()
{
    const int gid  = blockIdx.x * 8 + (threadIdx.x >> 5);   // 0..98303 == h*NTOK+tok
    const int lane = threadIdx.x & 31;
    const int h = gid / NTOK, tok = gid % NTOK;
    const float* zr = g_z + (size_t)tok * ZW + h * DLAT;
    float s = 0.f;
    #pragma unroll
    for (int q = 0; q < 8; q++) { float v = zr[lane + 32*q]; s = fmaf(v, v, s); }
    #pragma unroll
    for (int off = 16; off; off >>= 1) s += __shfl_down_sync(0xffffffffu, s, off);
    if (lane == 0) g_zz[gid] = s;
}

// ============================================================
// Kernel 3: cc[v] = sum_k cb[v,k]^2 for all three codebooks concatenated
// ============================================================
__global__ void cc_kernel(const float* __restrict__ cbc,
                          const float* __restrict__ cbp,
                          const float* __restrict__ cbt)
{
    const int gid  = blockIdx.x * 8 + (threadIdx.x >> 5);   // 0..2559
    const int lane = threadIdx.x & 31;
    const float* row;
    if (gid < VC)           row = cbc + (size_t)gid * DLAT;
    else if (gid < VC + VP) row = cbp + (size_t)(gid - VC) * DLAT;
    else                    row = cbt + (size_t)(gid - VC - VP) * DLAT;
    float s = 0.f;
    #pragma unroll
    for (int q = 0; q < 8; q++) { float v = row[lane + 32*q]; s = fmaf(v, v, s); }
    #pragma unroll
    for (int off = 16; off; off >>= 1) s += __shfl_down_sync(0xffffffffu, s, off);
    if (lane == 0) g_cc[gid] = s;
}

// ============================================================
// Kernel 4: scores + per-tile argmin. One launch per head.
// d = fl(zz + cc) - 2*dot  (matches reference rounding; 2*dot exact)
// Tile: 128 tokens x 128 codes, K=256. Partial (best,idx) per (tok, vtile).
// Ties resolved toward LOWER v at every level (first-occurrence argmin).
// ============================================================
__global__ __launch_bounds__(256, 2) void score_kernel(
    const float* __restrict__ cb, int h, int ccbase)
{
    const int vt = blockIdx.x;
    const int v0 = vt * 128;
    const int m0 = blockIdx.y * 128;

    __shared__ float As[8][128];
    __shared__ float Bs[8][128];
    __shared__ float rbest[128][16];
    __shared__ int   ridx[128][16];

    const int tid = threadIdx.x;
    const int tx = tid & 15, ty = tid >> 4;

    float acc[8][8];
    #pragma unroll
    for (int i = 0; i < 8; i++)
        #pragma unroll
        for (int j = 0; j < 8; j++) acc[i][j] = 0.f;

    const int arow = tid >> 1;
    const int akq  = (tid & 1) * 4;

    const float* aptr = g_z + (size_t)(m0 + arow) * ZW + h * DLAT + akq;
    const float* bptr = cb  + (size_t)(v0 + arow) * DLAT + akq;

    for (int k0 = 0; k0 < DLAT; k0 += 8) {
        float4 av = *(const float4*)(aptr + k0);
        float4 bv = *(const float4*)(bptr + k0);
        __syncthreads();
        As[akq+0][arow] = av.x; As[akq+1][arow] = av.y;
        As[akq+2][arow] = av.z; As[akq+3][arow] = av.w;
        Bs[akq+0][arow] = bv.x; Bs[akq+1][arow] = bv.y;
        Bs[akq+2][arow] = bv.z; Bs[akq+3][arow] = bv.w;
        __syncthreads();
        #pragma unroll
        for (int kk = 0; kk < 8; kk++) {
            float a[8], b[8];
            *(float4*)&a[0] = *(const float4*)&As[kk][ty*8];
            *(float4*)&a[4] = *(const float4*)&As[kk][ty*8+4];
            *(float4*)&b[0] = *(const float4*)&Bs[kk][tx*8];
            *(float4*)&b[4] = *(const float4*)&Bs[kk][tx*8+4];
            #pragma unroll
            for (int i = 0; i < 8; i++)
                #pragma unroll
                for (int j = 0; j < 8; j++)
                    acc[i][j] = fmaf(a[i], b[j], acc[i][j]);
        }
    }

    float zzv[8], ccv[8];
    #pragma unroll
    for (int i = 0; i < 8; i++) zzv[i] = g_zz[h * NTOK + m0 + ty*8 + i];
    #pragma unroll
    for (int j = 0; j < 8; j++) ccv[j] = g_cc[ccbase + v0 + tx*8 + j];

    #pragma unroll
    for (int i = 0; i < 8; i++) {
        float bbv = 3.402823466e38f; int bix = 0;
        #pragma unroll
        for (int j = 0; j < 8; j++) {           // ascending v within thread
            float t2 = zzv[i] + ccv[j];
            float s  = fmaf(-2.f, acc[i][j], t2);
            if (s < bbv) { bbv = s; bix = v0 + tx*8 + j; }
        }
        rbest[ty*8 + i][tx] = bbv;
        ridx [ty*8 + i][tx] = bix;
    }
    __syncthreads();

    if (tid < 128) {
        float bbv = rbest[tid][0]; int bix = ridx[tid][0];
        #pragma unroll
        for (int t = 1; t < 16; t++) {          // ascending tx == ascending v
            float c = rbest[tid][t];
            if (c < bbv) { bbv = c; bix = ridx[tid][t]; }
        }
        g_part[((size_t)h * NTOK + m0 + tid) * 8 + vt] =
            make_float2(bbv, __int_as_float(bix));
    }
}

// ============================================================
// Kernel 5: merge vtile partials -> final idx; gather; straight-through zq;
// write idx + zq to out, zq to aligned scratch, deterministic loss partial.
// Block: 64 tokens of one head.
// ============================================================
__global__ void merge_kernel(const float* __restrict__ cbc,
                             const float* __restrict__ cbp,
                             const float* __restrict__ cbt,
                             float* __restrict__ out)
{
    const int h  = blockIdx.y;
    const int m0 = blockIdx.x * 64;
    const int tid = threadIdx.x;
    const float* cb = (h == 0) ? cbc : ((h == 1) ? cbp : cbt);
    const int nvt = (h == 2) ? 4 : 8;

    __shared__ int sidx[64];
    if (tid < 64) {
        const float2* p = g_part + ((size_t)h * NTOK + m0 + tid) * 8;
        float2 v = p[0];
        float bbv = v.x; int bix = __float_as_int(v.y);
        for (int t = 1; t < nvt; t++) {         // ascending vtile, strict <
            float2 c = p[t];
            if (c.x < bbv) { bbv = c.x; bix = __float_as_int(c.y); }
        }
        sidx[tid] = bix;
        out[IDX_OFF + h * NTOK + m0 + tid] = (float)bix;
    }
    __syncthreads();

    float lsum = 0.f;
    for (int it = tid; it < 64 * DLAT; it += 256) {
        const int tok = it >> 8;
        const int k   = it & 255;
        const float zv = g_z[(size_t)(m0 + tok) * ZW + h * DLAT + k];
        const float cv = cb[(size_t)sidx[tok] * DLAT + k];
        const float zq = zv + (cv - zv);        // straight-through rounding, as reference
        out[ZQ_OFF + ((size_t)h * NTOK + m0 + tok) * DLAT + k] = zq;
        g_zq[(size_t)(m0 + tok) * ZW + h * DLAT + k] = zq;
        const float d = zv - zq;
        lsum = fmaf(d, d, lsum);
    }

    __shared__ float ws[8];
    #pragma unroll
    for (int off = 16; off; off >>= 1) lsum += __shfl_down_sync(0xffffffffu, lsum, off);
    if ((tid & 31) == 0) ws[tid >> 5] = lsum;
    __syncthreads();
    if (tid == 0) {
        float s = ws[0];
        #pragma unroll
        for (int w = 1; w < 8; w++) s += ws[w];
        g_losspart[h * 512 + blockIdx.x] = s;
    }
}

// ============================================================
// Kernel 6: deterministic loss finalize
// vq_loss = L + 0.25*L with L = (mse_c + mse_p + mse_t)/3
// ============================================================
__global__ void loss_kernel(float* __restrict__ out)
{
    __shared__ float sh[256];
    __shared__ float mh[3];
    const int tid = threadIdx.x;
    for (int h = 0; h < 3; h++) {
        sh[tid] = g_losspart[h*512 + tid] + g_losspart[h*512 + 256 + tid];
        __syncthreads();
        for (int off = 128; off; off >>= 1) {
            if (tid < off) sh[tid] += sh[tid + off];
            __syncthreads();
        }
        if (tid == 0) mh[h] = sh[0] / 8388608.0f;   // N = 32768*256
        __syncthreads();
    }
    if (tid == 0) {
        float L = (mh[0] + mh[1] + mh[2]) / 3.0f;
        out[LOSS_OFF] = fmaf(0.25f, L, L);          // 0.25*L exact -> same as two-step
    }
}

// ============================================================
// Kernel 7: x_recon = zq @ Wr + br   (128x128x8 SGEMM, K=768)
// ============================================================
__global__ __launch_bounds__(256, 2) void gemm_recon_kernel(
    const float* __restrict__ Wr, const float* __restrict__ br,
    float* __restrict__ out)
{
    const int n0 = blockIdx.x * 128;
    const int m0 = blockIdx.y * 128;

    __shared__ float As[8][128];
    __shared__ float Bs[8][128];

    const int tid = threadIdx.x;
    const int tx = tid & 15, ty = tid >> 4;

    float acc[8][8];
    #pragma unroll
    for (int i = 0; i < 8; i++)
        #pragma unroll
        for (int j = 0; j < 8; j++) acc[i][j] = 0.f;

    const int arow = tid >> 1;
    const int akq  = (tid & 1) * 4;
    const int bk   = tid >> 5;
    const int bn   = (tid & 31) * 4;

    const float* aptr = g_zq + (size_t)(m0 + arow) * ZW + akq;
    const float* bptr = Wr + (size_t)bk * INCH + n0 + bn;

    for (int k0 = 0; k0 < ZW; k0 += 8) {
        float4 av = *(const float4*)(aptr + k0);
        float4 bv = *(const float4*)(bptr + (size_t)k0 * INCH);
        __syncthreads();
        As[akq+0][arow] = av.x; As[akq+1][arow] = av.y;
        As[akq+2][arow] = av.z; As[akq+3][arow] = av.w;
        *(float4*)&Bs[bk][bn] = bv;
        __syncthreads();
        #pragma unroll
        for (int kk = 0; kk < 8; kk++) {
            float a[8], b[8];
            *(float4*)&a[0] = *(const float4*)&As[kk][ty*8];
            *(float4*)&a[4] = *(const float4*)&As[kk][ty*8+4];
            *(float4*)&b[0] = *(const float4*)&Bs[kk][tx*8];
            *(float4*)&b[4] = *(const float4*)&Bs[kk][tx*8+4];
            #pragma unroll
            for (int i = 0; i < 8; i++)
                #pragma unroll
                for (int j = 0; j < 8; j++)
                    acc[i][j] = fmaf(a[i], b[j], acc[i][j]);
        }
    }

    float bj[8];
    #pragma unroll
    for (int j = 0; j < 8; j++) bj[j] = br[n0 + tx*8 + j];

    #pragma unroll
    for (int i = 0; i < 8; i++) {
        float* orow = out + (size_t)(m0 + ty*8 + i) * INCH + n0 + tx*8;
        #pragma unroll
        for (int j = 0; j < 8; j += 4) {
            float4 v;
            v.x = acc[i][j+0] + bj[j+0];
            v.y = acc[i][j+1] + bj[j+1];
            v.z = acc[i][j+2] + bj[j+2];
            v.w = acc[i][j+3] + bj[j+3];
            *(float4*)&orow[j] = v;
        }
    }
}

// ============================================================
extern "C" void kernel_launch(void* const* d_in, const int* in_sizes, int n_in,
                              void* d_out, int out_size)
{
    (void)in_sizes; (void)n_in; (void)out_size;
    const float* x   = (const float*)d_in[0];
    const float* Wc  = (const float*)d_in[1];
    const float* bc  = (const float*)d_in[2];
    const float* Wp  = (const float*)d_in[3];
    const float* bp  = (const float*)d_in[4];
    const float* Wt  = (const float*)d_in[5];
    const float* bt  = (const float*)d_in[6];
    const float* cbc = (const float*)d_in[7];
    const float* cbp = (const float*)d_in[8];
    const float* cbt = (const float*)d_in[9];
    const float* Wr  = (const float*)d_in[10];
    const float* br  = (const float*)d_in[11];
    float* out = (float*)d_out;

    gemm_z_kernel<<<dim3(6, NTOK/128), 256>>>(x, Wc, Wp, Wt, bc, bp, bt);
    zz_kernel<<<(3*NTOK)/8, 256>>>();
    cc_kernel<<<(VC+VP+VT)/8, 256>>>(cbc, cbp, cbt);
    score_kernel<<<dim3(VC/128, NTOK/128), 256>>>(cbc, 0, 0);
    score_kernel<<<dim3(VP/128, NTOK/128), 256>>>(cbp, 1, VC);
    score_kernel<<<dim3(VT/128, NTOK/128), 256>>>(cbt, 2, VC+VP);
    merge_kernel<<<dim3(NTOK/64, 3), 256>>>(cbc, cbp, cbt, out);
    loss_kernel<<<1, 256>>>(out);
    gemm_recon_kernel<<<dim3(INCH/128, NTOK/128), 256>>>(Wr, br, out);
}

// round 5
// speedup vs baseline: 1.1441x; 1.1441x over previous
#include <cuda_runtime.h>
#include <cstdint>

#define NTOK 32768          // B*T = 16*2048
#define INCH 512
#define DLAT 256
#define ZW   768            // 3*DLAT
#define VC   1024
#define VP   1024
#define VT   512

// output layout: x_recon | vq_loss | idx_c | idx_p | idx_t | zq_c | zq_p | zq_t
#define LOSS_OFF (NTOK*INCH)
#define IDX_OFF  (LOSS_OFF + 1)
#define ZQ_OFF   (IDX_OFF + 3*NTOK)

#define MARGIN 3e-4f
#define CLIST_CAP 192

// -------- scratch --------
__device__ float  g_z[NTOK*ZW];
__device__ float  g_zq[NTOK*ZW];
__device__ float  g_zz[3*NTOK];
__device__ float  g_cc[VC+VP+VT];
__device__ float  g_sc[(size_t)NTOK*2560];   // screened r = cc - 2*dot (fp32)
__device__ float  g_tmin[3*NTOK*8];          // per (head,token,vtile) row min of r
__device__ int    g_idx[3*NTOK];
__device__ float  g_losspart[3*512];

// ============================================================
// Kernel 1: z = x @ [Wc|Wp|Wt] + b.  BITWISE IDENTICAL to R1's
// passing kernel (same per-(m,n) ascending-k fma chain, same
// epilogue adds); only smem double-buffering + prefetch added.
// ============================================================
__global__ __launch_bounds__(256, 2) void gemm_z_kernel(
    const float* __restrict__ x,
    const float* __restrict__ Wc, const float* __restrict__ Wp, const float* __restrict__ Wt,
    const float* __restrict__ bc, const float* __restrict__ bp, const float* __restrict__ bt)
{
    const int nt  = blockIdx.x;
    const int seg = nt >> 1;
    const float* W  = (seg == 0) ? Wc : (seg == 1 ? Wp : Wt);
    const float* bb = (seg == 0) ? bc : (seg == 1 ? bp : bt);
    const int nseg = (nt & 1) * 128;
    const int m0   = blockIdx.y * 128;

    __shared__ float As[2][8][128];
    __shared__ float Bs[2][8][128];

    const int tid = threadIdx.x;
    const int tx = tid & 15, ty = tid >> 4;

    float acc[8][8];
    #pragma unroll
    for (int i = 0; i < 8; i++)
        #pragma unroll
        for (int j = 0; j < 8; j++) acc[i][j] = 0.f;

    const int arow = tid >> 1;
    const int akq  = (tid & 1) * 4;
    const int bk   = tid >> 5;
    const int bn   = (tid & 31) * 4;

    const float* aptr = x + (size_t)(m0 + arow) * INCH + akq;
    const float* bptr = W + (size_t)bk * DLAT + nseg + bn;

    float4 av = *(const float4*)(aptr);
    float4 bv = *(const float4*)(bptr);
    As[0][akq+0][arow] = av.x; As[0][akq+1][arow] = av.y;
    As[0][akq+2][arow] = av.z; As[0][akq+3][arow] = av.w;
    *(float4*)&Bs[0][bk][bn] = bv;
    __syncthreads();

    for (int c = 0; c < 64; c++) {
        if (c + 1 < 64) {
            av = *(const float4*)(aptr + (c+1)*8);
            bv = *(const float4*)(bptr + (size_t)((c+1)*8) * DLAT);
        }
        const int cur = c & 1;
        #pragma unroll
        for (int kk = 0; kk < 8; kk++) {
            float a[8], b[8];
            *(float4*)&a[0] = *(const float4*)&As[cur][kk][ty*8];
            *(float4*)&a[4] = *(const float4*)&As[cur][kk][ty*8+4];
            *(float4*)&b[0] = *(const float4*)&Bs[cur][kk][tx*8];
            *(float4*)&b[4] = *(const float4*)&Bs[cur][kk][tx*8+4];
            #pragma unroll
            for (int i = 0; i < 8; i++)
                #pragma unroll
                for (int j = 0; j < 8; j++)
                    acc[i][j] = fmaf(a[i], b[j], acc[i][j]);
        }
        if (c + 1 < 64) {
            const int nb = (c + 1) & 1;
            As[nb][akq+0][arow] = av.x; As[nb][akq+1][arow] = av.y;
            As[nb][akq+2][arow] = av.z; As[nb][akq+3][arow] = av.w;
            *(float4*)&Bs[nb][bk][bn] = bv;
        }
        __syncthreads();
    }

    float bj[8];
    #pragma unroll
    for (int j = 0; j < 8; j++) bj[j] = bb[nseg + tx*8 + j];

    #pragma unroll
    for (int i = 0; i < 8; i++) {
        float* zrow = g_z + (size_t)(m0 + ty*8 + i) * ZW + nt * 128 + tx*8;
        #pragma unroll
        for (int j = 0; j < 8; j += 4) {
            float4 v;
            v.x = acc[i][j+0] + bj[j+0];
            v.y = acc[i][j+1] + bj[j+1];
            v.z = acc[i][j+2] + bj[j+2];
            v.w = acc[i][j+3] + bj[j+3];
            *(float4*)&zrow[j] = v;
        }
    }
}

// ============================================================
// Kernel 2/3: zz and cc — verbatim R1 (bitwise)
// ============================================================
__global__ void zz_kernel()
{
    const int gid  = blockIdx.x * 8 + (threadIdx.x >> 5);
    const int lane = threadIdx.x & 31;
    const int h = gid / NTOK, tok = gid % NTOK;
    const float* zr = g_z + (size_t)tok * ZW + h * DLAT;
    float s = 0.f;
    #pragma unroll
    for (int q = 0; q < 8; q++) { float v = zr[lane + 32*q]; s = fmaf(v, v, s); }
    #pragma unroll
    for (int off = 16; off; off >>= 1) s += __shfl_down_sync(0xffffffffu, s, off);
    if (lane == 0) g_zz[gid] = s;
}

__global__ void cc_kernel(const float* __restrict__ cbc,
                          const float* __restrict__ cbp,
                          const float* __restrict__ cbt)
{
    const int gid  = blockIdx.x * 8 + (threadIdx.x >> 5);
    const int lane = threadIdx.x & 31;
    const float* row;
    if (gid < VC)           row = cbc + (size_t)gid * DLAT;
    else if (gid < VC + VP) row = cbp + (size_t)(gid - VC) * DLAT;
    else                    row = cbt + (size_t)(gid - VC - VP) * DLAT;
    float s = 0.f;
    #pragma unroll
    for (int q = 0; q < 8; q++) { float v = row[lane + 32*q]; s = fmaf(v, v, s); }
    #pragma unroll
    for (int off = 16; off; off >>= 1) s += __shfl_down_sync(0xffffffffu, s, off);
    if (lane == 0) g_cc[gid] = s;
}

// ======================= tf32 mma machinery =======================
__device__ __forceinline__ uint32_t tf32_cvt(float x) {
    uint32_t r; asm("cvt.rna.tf32.f32 %0, %1;" : "=r"(r) : "f"(x)); return r;
}
__device__ __forceinline__ void mma8(float c[4], const uint32_t a[4], const uint32_t b[2]) {
    asm volatile("mma.sync.aligned.m16n8k8.row.col.f32.tf32.tf32.f32 "
        "{%0,%1,%2,%3},{%4,%5,%6,%7},{%8,%9},{%0,%1,%2,%3};"
        : "+f"(c[0]), "+f"(c[1]), "+f"(c[2]), "+f"(c[3])
        : "r"(a[0]), "r"(a[1]), "r"(a[2]), "r"(a[3]), "r"(b[0]), "r"(b[1]));
}

#define PAD 20

// ============================================================
// Kernel 4: SCREEN — 1xTF32, tile 128 tok x 128 codes, K=256.
// Writes r = fmaf(-2, dot_tf32, cc) for every (tok, code) to g_sc,
// plus per-(token, tile) row min to g_tmin.
// ============================================================
__global__ __launch_bounds__(256) void screen_mma(
    const float* __restrict__ cb, int h, int ccbase, int V, size_t scoff)
{
    extern __shared__ uint32_t sm[];       // 2 stages x (A 128xPAD + B 128xPAD)
    const int STG1 = 256 * PAD;
    __shared__ float s_cc[128];
    __shared__ float s_min[2][64][4];

    const int tid = threadIdx.x;
    const int vt = blockIdx.x, v0 = vt * 128;
    const int m0 = blockIdx.y * 128;
    if (tid < 128) s_cc[tid] = g_cc[ccbase + v0 + tid];

    float C[4][4][4];
    #pragma unroll
    for (int i = 0; i < 4; i++)
        #pragma unroll
        for (int j = 0; j < 4; j++)
            #pragma unroll
            for (int k = 0; k < 4; k++) C[i][j][k] = 0.f;

    const int arow = tid >> 2, akc = (tid & 3) * 4;
    const float* A = g_z + h * DLAT;
    const float* B = cb;

    float4 ra[2], rb[2];
    auto g2r = [&](int c) {
        const int k0 = c * 16;
        #pragma unroll
        for (int q = 0; q < 2; q++) {
            ra[q] = *(const float4*)(A + (size_t)(m0 + arow + q*64) * ZW + k0 + akc);
            rb[q] = *(const float4*)(B + (size_t)(v0 + arow + q*64) * DLAT + k0 + akc);
        }
    };
    auto r2s = [&](int s) {
        uint32_t* base = sm + s * STG1;
        #pragma unroll
        for (int q = 0; q < 2; q++) {
            float va[4] = {ra[q].x, ra[q].y, ra[q].z, ra[q].w};
            float vb[4] = {rb[q].x, rb[q].y, rb[q].z, rb[q].w};
            uint4 ha, hb;
            uint32_t* hap = (uint32_t*)&ha; uint32_t* hbp = (uint32_t*)&hb;
            #pragma unroll
            for (int i = 0; i < 4; i++) { hap[i] = tf32_cvt(va[i]); hbp[i] = tf32_cvt(vb[i]); }
            *(uint4*)(base + (arow + q*64)*PAD + akc) = ha;
            *(uint4*)(base + 128*PAD + (arow + q*64)*PAD + akc) = hb;
        }
    };

    const int lane = tid & 31, wid = tid >> 5;
    const int wm = wid >> 2, wn = wid & 3;
    const int g = lane >> 2, tg = lane & 3;

    g2r(0); r2s(0); __syncthreads();
    const int NC = DLAT / 16;   // 16
    for (int c = 0; c < NC; c++) {
        if (c + 1 < NC) g2r(c + 1);
        uint32_t* base = sm + (c & 1) * STG1;
        #pragma unroll
        for (int kk = 0; kk < 2; kk++) {
            const int kb = kk * 8 + tg;
            uint32_t ah[4][4], bh[4][2];
            #pragma unroll
            for (int ms = 0; ms < 4; ms++) {
                const int r = wm*64 + ms*16 + g;
                ah[ms][0] = base[r*PAD + kb];
                ah[ms][1] = base[(r+8)*PAD + kb];
                ah[ms][2] = base[r*PAD + kb + 4];
                ah[ms][3] = base[(r+8)*PAD + kb + 4];
            }
            #pragma unroll
            for (int ns = 0; ns < 4; ns++) {
                const int n = wn*32 + ns*8 + g;
                bh[ns][0] = base[128*PAD + n*PAD + kb];
                bh[ns][1] = base[128*PAD + n*PAD + kb + 4];
            }
            #pragma unroll
            for (int ms = 0; ms < 4; ms++)
                #pragma unroll
                for (int ns = 0; ns < 4; ns++) mma8(C[ms][ns], ah[ms], bh[ns]);
        }
        __syncthreads();
        if (c + 1 < NC) { r2s((c + 1) & 1); __syncthreads(); }
    }

    // epilogue: write r values + row-min reduction
    #pragma unroll
    for (int ms = 0; ms < 4; ms++) {
        #pragma unroll
        for (int half = 0; half < 2; half++) {
            const int lrow = wm*64 + ms*16 + g + half*8;
            float rmin = 3.402823466e38f;
            #pragma unroll
            for (int ns = 0; ns < 4; ns++) {
                const int col = wn*32 + ns*8 + tg*2;
                float r0 = fmaf(-2.f, C[ms][ns][half*2+0], s_cc[col]);
                float r1 = fmaf(-2.f, C[ms][ns][half*2+1], s_cc[col+1]);
                *(float2*)(g_sc + scoff + (size_t)(m0 + lrow) * V + v0 + col) =
                    make_float2(r0, r1);
                rmin = fminf(rmin, fminf(r0, r1));
            }
            #pragma unroll
            for (int o = 1; o < 4; o <<= 1)
                rmin = fminf(rmin, __shfl_xor_sync(0xffffffffu, rmin, o));
            if (tg == 0) s_min[wm][ms*16 + g + half*8][wn] = rmin;
        }
    }
    __syncthreads();
    if (tid < 128) {
        const int wm2 = tid >> 6, row = tid & 63;
        float m = fminf(fminf(s_min[wm2][row][0], s_min[wm2][row][1]),
                        fminf(s_min[wm2][row][2], s_min[wm2][row][3]));
        g_tmin[((size_t)h * NTOK + m0 + wm2*64 + row) * 8 + vt] = m;
    }
}

// ============================================================
// Kernel 5: RESCORE — exact fp32 re-evaluation of margin candidates.
// FIX vs R4: the threshold min-reduction now spans the FULL warp
// (o=16..1) so ALL 32 lanes hold the true row min; R4 left lanes
// 8-31 at FLT_MAX, flooding the candidate list with low indices.
// ============================================================
__global__ __launch_bounds__(256) void rescore_kernel(
    const float* __restrict__ cbc, const float* __restrict__ cbp,
    const float* __restrict__ cbt, float* __restrict__ out)
{
    __shared__ float zs[8][256];
    __shared__ int   clist[8][CLIST_CAP];

    const int h    = blockIdx.y;
    const int warp = threadIdx.x >> 5;
    const int lane = threadIdx.x & 31;
    const int tok  = blockIdx.x * 8 + warp;
    const int V      = (h == 2) ? VT : 1024;
    const int nvt    = (h == 2) ? 4 : 8;
    const int ccbase = (h == 0) ? 0 : (h == 1 ? VC : VC + VP);
    const size_t scoff = (h == 0) ? 0 : (h == 1 ? (size_t)NTOK*1024 : (size_t)2*NTOK*1024);
    const float* cb = (h == 0) ? cbc : (h == 1 ? cbp : cbt);

    const float* base = g_sc + scoff + (size_t)tok * V;

    // threshold from per-tile mins — FULL-WARP reduction (the R4 bug fix)
    float m = 3.402823466e38f;
    if (lane < nvt) m = g_tmin[((size_t)h * NTOK + tok) * 8 + lane];
    #pragma unroll
    for (int o = 16; o; o >>= 1) m = fminf(m, __shfl_xor_sync(0xffffffffu, m, o));
    const float thr = m + MARGIN;

    // stage z row
    const float* zrow = g_z + (size_t)tok * ZW + h * DLAT;
    #pragma unroll
    for (int q = 0; q < 8; q++) zs[warp][lane + 32*q] = zrow[lane + 32*q];
    __syncwarp();

    // collect candidates (ascending v)
    int cnt = 0;
    for (int i0 = 0; i0 < V; i0 += 32) {
        float r = base[i0 + lane];
        unsigned b = __ballot_sync(0xffffffffu, r <= thr);
        if (r <= thr) {
            int pos = cnt + __popc(b & ((1u << lane) - 1));
            if (pos < CLIST_CAP) clist[warp][pos] = i0 + lane;
        }
        cnt += __popc(b);
    }
    if (cnt > CLIST_CAP) cnt = CLIST_CAP;
    if (cnt == 0) { if (lane == 0) clist[warp][0] = 0; cnt = 1; }   // unreachable guard
    __syncwarp();

    // exact rescore: R1's bit pattern (serial ascending-k fma chain)
    const float zz = g_zz[h * NTOK + tok];
    float bs = 3.402823466e38f; int bv = 0x7fffffff;
    for (int ci = lane; ci < cnt; ci += 32) {
        const int v = clist[warp][ci];
        const float* cr = cb + (size_t)v * DLAT;
        float acc = 0.f;
        #pragma unroll 8
        for (int k = 0; k < 256; k++) acc = fmaf(zs[warp][k], cr[k], acc);
        const float sc = fmaf(-2.f, acc, zz + g_cc[ccbase + v]);
        if (sc < bs || (sc == bs && v < bv)) { bs = sc; bv = v; }
    }
    #pragma unroll
    for (int o = 16; o; o >>= 1) {
        float ob = __shfl_xor_sync(0xffffffffu, bs, o);
        int   ov = __shfl_xor_sync(0xffffffffu, bv, o);
        if (ob < bs || (ob == bs && ov < bv)) { bs = ob; bv = ov; }
    }
    if (lane == 0) {
        g_idx[h * NTOK + tok] = bv;
        out[IDX_OFF + h * NTOK + tok] = (float)bv;
    }
}

// ============================================================
// Kernel 6: merge — gather zq, loss partials (R1 bitwise; idx from g_idx)
// ============================================================
__global__ void merge_kernel(const float* __restrict__ cbc,
                             const float* __restrict__ cbp,
                             const float* __restrict__ cbt,
                             float* __restrict__ out)
{
    const int h  = blockIdx.y;
    const int m0 = blockIdx.x * 64;
    const int tid = threadIdx.x;
    const float* cb = (h == 0) ? cbc : ((h == 1) ? cbp : cbt);

    __shared__ int sidx[64];
    if (tid < 64) sidx[tid] = g_idx[h * NTOK + m0 + tid];
    __syncthreads();

    float lsum = 0.f;
    for (int it = tid; it < 64 * DLAT; it += 256) {
        const int tok = it >> 8;
        const int k   = it & 255;
        const float zv = g_z[(size_t)(m0 + tok) * ZW + h * DLAT + k];
        const float cv = cb[(size_t)sidx[tok] * DLAT + k];
        const float zq = zv + (cv - zv);
        out[ZQ_OFF + ((size_t)h * NTOK + m0 + tok) * DLAT + k] = zq;
        g_zq[(size_t)(m0 + tok) * ZW + h * DLAT + k] = zq;
        const float d = zv - zq;
        lsum = fmaf(d, d, lsum);
    }

    __shared__ float ws[8];
    #pragma unroll
    for (int off = 16; off; off >>= 1) lsum += __shfl_down_sync(0xffffffffu, lsum, off);
    if ((tid & 31) == 0) ws[tid >> 5] = lsum;
    __syncthreads();
    if (tid == 0) {
        float s = ws[0];
        #pragma unroll
        for (int w = 1; w < 8; w++) s += ws[w];
        g_losspart[h * 512 + blockIdx.x] = s;
    }
}

// ============================================================
// Kernel 7: loss finalize (verbatim R1)
// ============================================================
__global__ void loss_kernel(float* __restrict__ out)
{
    __shared__ float sh[256];
    __shared__ float mh[3];
    const int tid = threadIdx.x;
    for (int h = 0; h < 3; h++) {
        sh[tid] = g_losspart[h*512 + tid] + g_losspart[h*512 + 256 + tid];
        __syncthreads();
        for (int off = 128; off; off >>= 1) {
            if (tid < off) sh[tid] += sh[tid + off];
            __syncthreads();
        }
        if (tid == 0) mh[h] = sh[0] / 8388608.0f;
        __syncthreads();
    }
    if (tid == 0) {
        float L = (mh[0] + mh[1] + mh[2]) / 3.0f;
        out[LOSS_OFF] = fmaf(0.25f, L, L);
    }
}

// ============================================================
// Kernel 8: recon — 3xTF32 (fp32-class accuracy), K=768
// ============================================================
#define OFF3_ALO (128*PAD)
#define OFF3_BHI (256*PAD)
#define OFF3_BLO (384*PAD)
#define STG3     (512*PAD)
#define SMEM_DYN3 (2*STG3*4)

__global__ __launch_bounds__(256) void recon_mma(
    const float* __restrict__ Wr, const float* __restrict__ br,
    float* __restrict__ out)
{
    extern __shared__ uint32_t sm[];
    __shared__ float s_col[128];

    const int tid = threadIdx.x;
    const int n0 = blockIdx.x * 128;
    const int m0 = blockIdx.y * 128;
    if (tid < 128) s_col[tid] = br[n0 + tid];

    float C[4][4][4];
    #pragma unroll
    for (int i = 0; i < 4; i++)
        #pragma unroll
        for (int j = 0; j < 4; j++)
            #pragma unroll
            for (int k = 0; k < 4; k++) C[i][j][k] = 0.f;

    const int arow = tid >> 2, akc = (tid & 3) * 4;
    const int bk   = tid >> 5, bnc = (tid & 31) * 4;

    float4 ra[2], rb[2];
    const int NC = ZW / 16;   // 48

    auto g2r = [&](int c) {
        const int k0 = c * 16;
        #pragma unroll
        for (int q = 0; q < 2; q++) {
            ra[q] = *(const float4*)(g_zq + (size_t)(m0 + arow + q*64) * ZW + k0 + akc);
            rb[q] = *(const float4*)(Wr + (size_t)(k0 + bk + q*8) * INCH + n0 + bnc);
        }
    };
    auto r2s = [&](int s) {
        uint32_t* base = sm + s * STG3;
        #pragma unroll
        for (int q = 0; q < 2; q++) {
            float v[4] = {ra[q].x, ra[q].y, ra[q].z, ra[q].w};
            uint4 hh, ll;
            uint32_t* hp = (uint32_t*)&hh; uint32_t* lp = (uint32_t*)&ll;
            #pragma unroll
            for (int i = 0; i < 4; i++) {
                hp[i] = tf32_cvt(v[i]);
                lp[i] = tf32_cvt(v[i] - __uint_as_float(hp[i]));
            }
            *(uint4*)(base + (arow + q*64)*PAD + akc) = hh;
            *(uint4*)(base + OFF3_ALO + (arow + q*64)*PAD + akc) = ll;
        }
        #pragma unroll
        for (int q = 0; q < 2; q++) {
            float v[4] = {rb[q].x, rb[q].y, rb[q].z, rb[q].w};
            #pragma unroll
            for (int i = 0; i < 4; i++) {
                uint32_t hv = tf32_cvt(v[i]);
                base[OFF3_BHI + (bnc + i)*PAD + bk + q*8] = hv;
                base[OFF3_BLO + (bnc + i)*PAD + bk + q*8] =
                    tf32_cvt(v[i] - __uint_as_float(hv));
            }
        }
    };

    const int lane = tid & 31, wid = tid >> 5;
    const int wm = wid >> 2, wn = wid & 3;
    const int g = lane >> 2, tg = lane & 3;

    g2r(0); r2s(0); __syncthreads();

    for (int c = 0; c < NC; c++) {
        if (c + 1 < NC) g2r(c + 1);
        uint32_t* base = sm + (c & 1) * STG3;
        #pragma unroll
        for (int kk = 0; kk < 2; kk++) {
            const int kb = kk * 8 + tg;
            uint32_t ah[4][4], al[4][4], bh[4][2], bl[4][2];
            #pragma unroll
            for (int ms = 0; ms < 4; ms++) {
                const int r = wm*64 + ms*16 + g;
                ah[ms][0] = base[r*PAD + kb];
                ah[ms][1] = base[(r+8)*PAD + kb];
                ah[ms][2] = base[r*PAD + kb + 4];
                ah[ms][3] = base[(r+8)*PAD + kb + 4];
                al[ms][0] = base[OFF3_ALO + r*PAD + kb];
                al[ms][1] = base[OFF3_ALO + (r+8)*PAD + kb];
                al[ms][2] = base[OFF3_ALO + r*PAD + kb + 4];
                al[ms][3] = base[OFF3_ALO + (r+8)*PAD + kb + 4];
            }
            #pragma unroll
            for (int ns = 0; ns < 4; ns++) {
                const int n = wn*32 + ns*8 + g;
                bh[ns][0] = base[OFF3_BHI + n*PAD + kb];
                bh[ns][1] = base[OFF3_BHI + n*PAD + kb + 4];
                bl[ns][0] = base[OFF3_BLO + n*PAD + kb];
                bl[ns][1] = base[OFF3_BLO + n*PAD + kb + 4];
            }
            #pragma unroll
            for (int ms = 0; ms < 4; ms++)
                #pragma unroll
                for (int ns = 0; ns < 4; ns++) mma8(C[ms][ns], ah[ms], bh[ns]);
            #pragma unroll
            for (int ms = 0; ms < 4; ms++)
                #pragma unroll
                for (int ns = 0; ns < 4; ns++) mma8(C[ms][ns], ah[ms], bl[ns]);
            #pragma unroll
            for (int ms = 0; ms < 4; ms++)
                #pragma unroll
                for (int ns = 0; ns < 4; ns++) mma8(C[ms][ns], al[ms], bh[ns]);
        }
        __syncthreads();
        if (c + 1 < NC) { r2s((c + 1) & 1); __syncthreads(); }
    }

    #pragma unroll
    for (int ms = 0; ms < 4; ms++) {
        const int row = m0 + wm*64 + ms*16 + g;
        #pragma unroll
        for (int ns = 0; ns < 4; ns++) {
            const int col = wn*32 + ns*8 + tg*2;
            float2 v0 = make_float2(C[ms][ns][0] + s_col[col], C[ms][ns][1] + s_col[col+1]);
            float2 v1 = make_float2(C[ms][ns][2] + s_col[col], C[ms][ns][3] + s_col[col+1]);
            *(float2*)(out + (size_t)row * INCH + n0 + col) = v0;
            *(float2*)(out + (size_t)(row+8) * INCH + n0 + col) = v1;
        }
    }
}

// ============================================================
extern "C" void kernel_launch(void* const* d_in, const int* in_sizes, int n_in,
                              void* d_out, int out_size)
{
    (void)in_sizes; (void)n_in; (void)out_size;
    const float* x   = (const float*)d_in[0];
    const float* Wc  = (const float*)d_in[1];
    const float* bc  = (const float*)d_in[2];
    const float* Wp  = (const float*)d_in[3];
    const float* bp  = (const float*)d_in[4];
    const float* Wt  = (const float*)d_in[5];
    const float* bt  = (const float*)d_in[6];
    const float* cbc = (const float*)d_in[7];
    const float* cbp = (const float*)d_in[8];
    const float* cbt = (const float*)d_in[9];
    const float* Wr  = (const float*)d_in[10];
    const float* br  = (const float*)d_in[11];
    float* out = (float*)d_out;

    const int SMEM_DYN1 = 2 * (256 * PAD) * 4;   // 40960
    cudaFuncSetAttribute(screen_mma, cudaFuncAttributeMaxDynamicSharedMemorySize, SMEM_DYN1);
    cudaFuncSetAttribute(recon_mma,  cudaFuncAttributeMaxDynamicSharedMemorySize, SMEM_DYN3);

    gemm_z_kernel<<<dim3(6, NTOK/128), 256>>>(x, Wc, Wp, Wt, bc, bp, bt);
    zz_kernel<<<(3*NTOK)/8, 256>>>();
    cc_kernel<<<(VC+VP+VT)/8, 256>>>(cbc, cbp, cbt);
    screen_mma<<<dim3(VC/128, NTOK/128), 256, SMEM_DYN1>>>(cbc, 0, 0, 1024, 0);
    screen_mma<<<dim3(VP/128, NTOK/128), 256, SMEM_DYN1>>>(cbp, 1, VC, 1024, (size_t)NTOK*1024);
    screen_mma<<<dim3(VT/128, NTOK/128), 256, SMEM_DYN1>>>(cbt, 2, VC+VP, 512, (size_t)2*NTOK*1024);
    rescore_kernel<<<dim3(NTOK/8, 3), 256>>>(cbc, cbp, cbt, out);
    merge_kernel<<<dim3(NTOK/64, 3), 256>>>(cbc, cbp, cbt, out);
    loss_kernel<<<1, 256>>>(out);
    recon_mma<<<dim3(INCH/128, NTOK/128), 256, SMEM_DYN3>>>(Wr, br, out);
}

// round 6
// speedup vs baseline: 1.7955x; 1.5693x over previous
#include <cuda_runtime.h>
#include <cstdint>

#define NTOK 32768          // B*T = 16*2048
#define INCH 512
#define DLAT 256
#define ZW   768            // 3*DLAT
#define VC   1024
#define VP   1024
#define VT   512
#define VTOT (VC+VP+VT)     // 2560

// output layout: x_recon | vq_loss | idx_c | idx_p | idx_t | zq_c | zq_p | zq_t
#define LOSS_OFF (NTOK*INCH)
#define IDX_OFF  (LOSS_OFF + 1)
#define ZQ_OFF   (IDX_OFF + 3*NTOK)

#define MARGIN 3e-4f
#define CLIST_CAP 192

// -------- scratch --------
__device__ float  g_z[NTOK*ZW];
__device__ float  g_zz[3*NTOK];
__device__ float  g_cc[VTOT];
__device__ float  g_sc[(size_t)NTOK*2560];   // screened r = cc - 2*dot (fp32)
__device__ float  g_tmin[3*NTOK*8];          // per (head,token,vtile) row min of r
__device__ int    g_idx[3*NTOK];
__device__ float  g_losspart[3*512];
__device__ float  g_P[VTOT*INCH];            // P_h = cb_h @ Wr_h  (5.2 MB)

// ============================================================
// Kernel 1: z = x @ [Wc|Wp|Wt] + b.  BITWISE IDENTICAL to R1/R5.
// ============================================================
__global__ __launch_bounds__(256, 2) void gemm_z_kernel(
    const float* __restrict__ x,
    const float* __restrict__ Wc, const float* __restrict__ Wp, const float* __restrict__ Wt,
    const float* __restrict__ bc, const float* __restrict__ bp, const float* __restrict__ bt)
{
    const int nt  = blockIdx.x;
    const int seg = nt >> 1;
    const float* W  = (seg == 0) ? Wc : (seg == 1 ? Wp : Wt);
    const float* bb = (seg == 0) ? bc : (seg == 1 ? bp : bt);
    const int nseg = (nt & 1) * 128;
    const int m0   = blockIdx.y * 128;

    __shared__ float As[2][8][128];
    __shared__ float Bs[2][8][128];

    const int tid = threadIdx.x;
    const int tx = tid & 15, ty = tid >> 4;

    float acc[8][8];
    #pragma unroll
    for (int i = 0; i < 8; i++)
        #pragma unroll
        for (int j = 0; j < 8; j++) acc[i][j] = 0.f;

    const int arow = tid >> 1;
    const int akq  = (tid & 1) * 4;
    const int bk   = tid >> 5;
    const int bn   = (tid & 31) * 4;

    const float* aptr = x + (size_t)(m0 + arow) * INCH + akq;
    const float* bptr = W + (size_t)bk * DLAT + nseg + bn;

    float4 av = *(const float4*)(aptr);
    float4 bv = *(const float4*)(bptr);
    As[0][akq+0][arow] = av.x; As[0][akq+1][arow] = av.y;
    As[0][akq+2][arow] = av.z; As[0][akq+3][arow] = av.w;
    *(float4*)&Bs[0][bk][bn] = bv;
    __syncthreads();

    for (int c = 0; c < 64; c++) {
        if (c + 1 < 64) {
            av = *(const float4*)(aptr + (c+1)*8);
            bv = *(const float4*)(bptr + (size_t)((c+1)*8) * DLAT);
        }
        const int cur = c & 1;
        #pragma unroll
        for (int kk = 0; kk < 8; kk++) {
            float a[8], b[8];
            *(float4*)&a[0] = *(const float4*)&As[cur][kk][ty*8];
            *(float4*)&a[4] = *(const float4*)&As[cur][kk][ty*8+4];
            *(float4*)&b[0] = *(const float4*)&Bs[cur][kk][tx*8];
            *(float4*)&b[4] = *(const float4*)&Bs[cur][kk][tx*8+4];
            #pragma unroll
            for (int i = 0; i < 8; i++)
                #pragma unroll
                for (int j = 0; j < 8; j++)
                    acc[i][j] = fmaf(a[i], b[j], acc[i][j]);
        }
        if (c + 1 < 64) {
            const int nb = (c + 1) & 1;
            As[nb][akq+0][arow] = av.x; As[nb][akq+1][arow] = av.y;
            As[nb][akq+2][arow] = av.z; As[nb][akq+3][arow] = av.w;
            *(float4*)&Bs[nb][bk][bn] = bv;
        }
        __syncthreads();
    }

    float bj[8];
    #pragma unroll
    for (int j = 0; j < 8; j++) bj[j] = bb[nseg + tx*8 + j];

    #pragma unroll
    for (int i = 0; i < 8; i++) {
        float* zrow = g_z + (size_t)(m0 + ty*8 + i) * ZW + nt * 128 + tx*8;
        #pragma unroll
        for (int j = 0; j < 8; j += 4) {
            float4 v;
            v.x = acc[i][j+0] + bj[j+0];
            v.y = acc[i][j+1] + bj[j+1];
            v.z = acc[i][j+2] + bj[j+2];
            v.w = acc[i][j+3] + bj[j+3];
            *(float4*)&zrow[j] = v;
        }
    }
}

// ============================================================
// Kernel 2/3: zz and cc — verbatim (bitwise)
// ============================================================
__global__ void zz_kernel()
{
    const int gid  = blockIdx.x * 8 + (threadIdx.x >> 5);
    const int lane = threadIdx.x & 31;
    const int h = gid / NTOK, tok = gid % NTOK;
    const float* zr = g_z + (size_t)tok * ZW + h * DLAT;
    float s = 0.f;
    #pragma unroll
    for (int q = 0; q < 8; q++) { float v = zr[lane + 32*q]; s = fmaf(v, v, s); }
    #pragma unroll
    for (int off = 16; off; off >>= 1) s += __shfl_down_sync(0xffffffffu, s, off);
    if (lane == 0) g_zz[gid] = s;
}

__global__ void cc_kernel(const float* __restrict__ cbc,
                          const float* __restrict__ cbp,
                          const float* __restrict__ cbt)
{
    const int gid  = blockIdx.x * 8 + (threadIdx.x >> 5);
    const int lane = threadIdx.x & 31;
    const float* row;
    if (gid < VC)           row = cbc + (size_t)gid * DLAT;
    else if (gid < VC + VP) row = cbp + (size_t)(gid - VC) * DLAT;
    else                    row = cbt + (size_t)(gid - VC - VP) * DLAT;
    float s = 0.f;
    #pragma unroll
    for (int q = 0; q < 8; q++) { float v = row[lane + 32*q]; s = fmaf(v, v, s); }
    #pragma unroll
    for (int off = 16; off; off >>= 1) s += __shfl_down_sync(0xffffffffu, s, off);
    if (lane == 0) g_cc[gid] = s;
}

// ======================= tf32 mma machinery =======================
__device__ __forceinline__ uint32_t tf32_cvt(float x) {
    uint32_t r; asm("cvt.rna.tf32.f32 %0, %1;" : "=r"(r) : "f"(x)); return r;
}
__device__ __forceinline__ void mma8(float c[4], const uint32_t a[4], const uint32_t b[2]) {
    asm volatile("mma.sync.aligned.m16n8k8.row.col.f32.tf32.tf32.f32 "
        "{%0,%1,%2,%3},{%4,%5,%6,%7},{%8,%9},{%0,%1,%2,%3};"
        : "+f"(c[0]), "+f"(c[1]), "+f"(c[2]), "+f"(c[3])
        : "r"(a[0]), "r"(a[1]), "r"(a[2]), "r"(a[3]), "r"(b[0]), "r"(b[1]));
}

#define PAD 20

// ============================================================
// Kernel 4: SCREEN — 1xTF32 (unchanged from R5)
// ============================================================
__global__ __launch_bounds__(256) void screen_mma(
    const float* __restrict__ cb, int h, int ccbase, int V, size_t scoff)
{
    extern __shared__ uint32_t sm[];
    const int STG1 = 256 * PAD;
    __shared__ float s_cc[128];
    __shared__ float s_min[2][64][4];

    const int tid = threadIdx.x;
    const int vt = blockIdx.x, v0 = vt * 128;
    const int m0 = blockIdx.y * 128;
    if (tid < 128) s_cc[tid] = g_cc[ccbase + v0 + tid];

    float C[4][4][4];
    #pragma unroll
    for (int i = 0; i < 4; i++)
        #pragma unroll
        for (int j = 0; j < 4; j++)
            #pragma unroll
            for (int k = 0; k < 4; k++) C[i][j][k] = 0.f;

    const int arow = tid >> 2, akc = (tid & 3) * 4;
    const float* A = g_z + h * DLAT;
    const float* B = cb;

    float4 ra[2], rb[2];
    auto g2r = [&](int c) {
        const int k0 = c * 16;
        #pragma unroll
        for (int q = 0; q < 2; q++) {
            ra[q] = *(const float4*)(A + (size_t)(m0 + arow + q*64) * ZW + k0 + akc);
            rb[q] = *(const float4*)(B + (size_t)(v0 + arow + q*64) * DLAT + k0 + akc);
        }
    };
    auto r2s = [&](int s) {
        uint32_t* base = sm + s * STG1;
        #pragma unroll
        for (int q = 0; q < 2; q++) {
            float va[4] = {ra[q].x, ra[q].y, ra[q].z, ra[q].w};
            float vb[4] = {rb[q].x, rb[q].y, rb[q].z, rb[q].w};
            uint4 ha, hb;
            uint32_t* hap = (uint32_t*)&ha; uint32_t* hbp = (uint32_t*)&hb;
            #pragma unroll
            for (int i = 0; i < 4; i++) { hap[i] = tf32_cvt(va[i]); hbp[i] = tf32_cvt(vb[i]); }
            *(uint4*)(base + (arow + q*64)*PAD + akc) = ha;
            *(uint4*)(base + 128*PAD + (arow + q*64)*PAD + akc) = hb;
        }
    };

    const int lane = tid & 31, wid = tid >> 5;
    const int wm = wid >> 2, wn = wid & 3;
    const int g = lane >> 2, tg = lane & 3;

    g2r(0); r2s(0); __syncthreads();
    const int NC = DLAT / 16;   // 16
    for (int c = 0; c < NC; c++) {
        if (c + 1 < NC) g2r(c + 1);
        uint32_t* base = sm + (c & 1) * STG1;
        #pragma unroll
        for (int kk = 0; kk < 2; kk++) {
            const int kb = kk * 8 + tg;
            uint32_t ah[4][4], bh[4][2];
            #pragma unroll
            for (int ms = 0; ms < 4; ms++) {
                const int r = wm*64 + ms*16 + g;
                ah[ms][0] = base[r*PAD + kb];
                ah[ms][1] = base[(r+8)*PAD + kb];
                ah[ms][2] = base[r*PAD + kb + 4];
                ah[ms][3] = base[(r+8)*PAD + kb + 4];
            }
            #pragma unroll
            for (int ns = 0; ns < 4; ns++) {
                const int n = wn*32 + ns*8 + g;
                bh[ns][0] = base[128*PAD + n*PAD + kb];
                bh[ns][1] = base[128*PAD + n*PAD + kb + 4];
            }
            #pragma unroll
            for (int ms = 0; ms < 4; ms++)
                #pragma unroll
                for (int ns = 0; ns < 4; ns++) mma8(C[ms][ns], ah[ms], bh[ns]);
        }
        __syncthreads();
        if (c + 1 < NC) { r2s((c + 1) & 1); __syncthreads(); }
    }

    #pragma unroll
    for (int ms = 0; ms < 4; ms++) {
        #pragma unroll
        for (int half = 0; half < 2; half++) {
            const int lrow = wm*64 + ms*16 + g + half*8;
            float rmin = 3.402823466e38f;
            #pragma unroll
            for (int ns = 0; ns < 4; ns++) {
                const int col = wn*32 + ns*8 + tg*2;
                float r0 = fmaf(-2.f, C[ms][ns][half*2+0], s_cc[col]);
                float r1 = fmaf(-2.f, C[ms][ns][half*2+1], s_cc[col+1]);
                *(float2*)(g_sc + scoff + (size_t)(m0 + lrow) * V + v0 + col) =
                    make_float2(r0, r1);
                rmin = fminf(rmin, fminf(r0, r1));
            }
            #pragma unroll
            for (int o = 1; o < 4; o <<= 1)
                rmin = fminf(rmin, __shfl_xor_sync(0xffffffffu, rmin, o));
            if (tg == 0) s_min[wm][ms*16 + g + half*8][wn] = rmin;
        }
    }
    __syncthreads();
    if (tid < 128) {
        const int wm2 = tid >> 6, row = tid & 63;
        float m = fminf(fminf(s_min[wm2][row][0], s_min[wm2][row][1]),
                        fminf(s_min[wm2][row][2], s_min[wm2][row][3]));
        g_tmin[((size_t)h * NTOK + m0 + wm2*64 + row) * 8 + vt] = m;
    }
}

// ============================================================
// Kernel 5: RESCORE — exact fp32 (unchanged from R5, incl. warp fix)
// ============================================================
__global__ __launch_bounds__(256) void rescore_kernel(
    const float* __restrict__ cbc, const float* __restrict__ cbp,
    const float* __restrict__ cbt, float* __restrict__ out)
{
    __shared__ float zs[8][256];
    __shared__ int   clist[8][CLIST_CAP];

    const int h    = blockIdx.y;
    const int warp = threadIdx.x >> 5;
    const int lane = threadIdx.x & 31;
    const int tok  = blockIdx.x * 8 + warp;
    const int V      = (h == 2) ? VT : 1024;
    const int nvt    = (h == 2) ? 4 : 8;
    const int ccbase = (h == 0) ? 0 : (h == 1 ? VC : VC + VP);
    const size_t scoff = (h == 0) ? 0 : (h == 1 ? (size_t)NTOK*1024 : (size_t)2*NTOK*1024);
    const float* cb = (h == 0) ? cbc : (h == 1 ? cbp : cbt);

    const float* base = g_sc + scoff + (size_t)tok * V;

    float m = 3.402823466e38f;
    if (lane < nvt) m = g_tmin[((size_t)h * NTOK + tok) * 8 + lane];
    #pragma unroll
    for (int o = 16; o; o >>= 1) m = fminf(m, __shfl_xor_sync(0xffffffffu, m, o));
    const float thr = m + MARGIN;

    const float* zrow = g_z + (size_t)tok * ZW + h * DLAT;
    #pragma unroll
    for (int q = 0; q < 8; q++) zs[warp][lane + 32*q] = zrow[lane + 32*q];
    __syncwarp();

    int cnt = 0;
    for (int i0 = 0; i0 < V; i0 += 32) {
        float r = base[i0 + lane];
        unsigned b = __ballot_sync(0xffffffffu, r <= thr);
        if (r <= thr) {
            int pos = cnt + __popc(b & ((1u << lane) - 1));
            if (pos < CLIST_CAP) clist[warp][pos] = i0 + lane;
        }
        cnt += __popc(b);
    }
    if (cnt > CLIST_CAP) cnt = CLIST_CAP;
    if (cnt == 0) { if (lane == 0) clist[warp][0] = 0; cnt = 1; }
    __syncwarp();

    const float zz = g_zz[h * NTOK + tok];
    float bs = 3.402823466e38f; int bv = 0x7fffffff;
    for (int ci = lane; ci < cnt; ci += 32) {
        const int v = clist[warp][ci];
        const float* cr = cb + (size_t)v * DLAT;
        float acc = 0.f;
        #pragma unroll 8
        for (int k = 0; k < 256; k++) acc = fmaf(zs[warp][k], cr[k], acc);
        const float sc = fmaf(-2.f, acc, zz + g_cc[ccbase + v]);
        if (sc < bs || (sc == bs && v < bv)) { bs = sc; bv = v; }
    }
    #pragma unroll
    for (int o = 16; o; o >>= 1) {
        float ob = __shfl_xor_sync(0xffffffffu, bs, o);
        int   ov = __shfl_xor_sync(0xffffffffu, bv, o);
        if (ob < bs || (ob == bs && ov < bv)) { bs = ob; bv = ov; }
    }
    if (lane == 0) {
        g_idx[h * NTOK + tok] = bv;
        out[IDX_OFF + h * NTOK + tok] = (float)bv;
    }
}

// ============================================================
// Kernel 6: merge — gather zq to out, loss partials (g_zq write removed)
// ============================================================
__global__ void merge_kernel(const float* __restrict__ cbc,
                             const float* __restrict__ cbp,
                             const float* __restrict__ cbt,
                             float* __restrict__ out)
{
    const int h  = blockIdx.y;
    const int m0 = blockIdx.x * 64;
    const int tid = threadIdx.x;
    const float* cb = (h == 0) ? cbc : ((h == 1) ? cbp : cbt);

    __shared__ int sidx[64];
    if (tid < 64) sidx[tid] = g_idx[h * NTOK + m0 + tid];
    __syncthreads();

    float lsum = 0.f;
    for (int it = tid; it < 64 * DLAT; it += 256) {
        const int tok = it >> 8;
        const int k   = it & 255;
        const float zv = g_z[(size_t)(m0 + tok) * ZW + h * DLAT + k];
        const float cv = cb[(size_t)sidx[tok] * DLAT + k];
        const float zq = zv + (cv - zv);
        out[ZQ_OFF + ((size_t)h * NTOK + m0 + tok) * DLAT + k] = zq;
        const float d = zv - zq;
        lsum = fmaf(d, d, lsum);
    }

    __shared__ float ws[8];
    #pragma unroll
    for (int off = 16; off; off >>= 1) lsum += __shfl_down_sync(0xffffffffu, lsum, off);
    if ((tid & 31) == 0) ws[tid >> 5] = lsum;
    __syncthreads();
    if (tid == 0) {
        float s = ws[0];
        #pragma unroll
        for (int w = 1; w < 8; w++) s += ws[w];
        g_losspart[h * 512 + blockIdx.x] = s;
    }
}

// ============================================================
// Kernel 7: loss finalize (verbatim)
// ============================================================
__global__ void loss_kernel(float* __restrict__ out)
{
    __shared__ float sh[256];
    __shared__ float mh[3];
    const int tid = threadIdx.x;
    for (int h = 0; h < 3; h++) {
        sh[tid] = g_losspart[h*512 + tid] + g_losspart[h*512 + 256 + tid];
        __syncthreads();
        for (int off = 128; off; off >>= 1) {
            if (tid < off) sh[tid] += sh[tid + off];
            __syncthreads();
        }
        if (tid == 0) mh[h] = sh[0] / 8388608.0f;
        __syncthreads();
    }
    if (tid == 0) {
        float L = (mh[0] + mh[1] + mh[2]) / 3.0f;
        out[LOSS_OFF] = fmaf(0.25f, L, L);
    }
}

// ============================================================
// Kernel 8: PPROJ — P_h = cb_h @ Wr_h  ([2560,256]x[256,512] tiles).
// SIMT fp32 tiled GEMM, 64x64 tiles, K=256. ~0.67 GFLOP total.
// Row blocks never straddle head boundaries (all multiples of 64).
// ============================================================
__global__ __launch_bounds__(256) void pproj_kernel(
    const float* __restrict__ cbc, const float* __restrict__ cbp,
    const float* __restrict__ cbt, const float* __restrict__ Wr)
{
    __shared__ float As[64][17];   // [m][k] padded
    __shared__ float Bs[16][64];   // [k][n]

    const int m0 = blockIdx.x * 64;       // global code row
    const int n0 = blockIdx.y * 64;
    const int tid = threadIdx.x;
    const int tx = tid & 15, ty = tid >> 4;

    const float* cb; int mloc, kbase;
    if (m0 < VC)           { cb = cbc; mloc = m0;            kbase = 0;   }
    else if (m0 < VC + VP) { cb = cbp; mloc = m0 - VC;       kbase = 256; }
    else                   { cb = cbt; mloc = m0 - VC - VP;  kbase = 512; }

    float acc[4][4];
    #pragma unroll
    for (int i = 0; i < 4; i++)
        #pragma unroll
        for (int j = 0; j < 4; j++) acc[i][j] = 0.f;

    const int arow = tid >> 2, akc = (tid & 3) * 4;
    const int bkr  = tid >> 4, bnc = (tid & 15) * 4;

    for (int k0 = 0; k0 < DLAT; k0 += 16) {
        float4 av = *(const float4*)(cb + (size_t)(mloc + arow) * DLAT + k0 + akc);
        float4 bvv = *(const float4*)(Wr + (size_t)(kbase + k0 + bkr) * INCH + n0 + bnc);
        As[arow][akc+0] = av.x; As[arow][akc+1] = av.y;
        As[arow][akc+2] = av.z; As[arow][akc+3] = av.w;
        *(float4*)&Bs[bkr][bnc] = bvv;
        __syncthreads();
        #pragma unroll
        for (int k = 0; k < 16; k++) {
            float a[4], b[4];
            #pragma unroll
            for (int i = 0; i < 4; i++) a[i] = As[ty*4 + i][k];
            *(float4*)&b[0] = *(const float4*)&Bs[k][tx*4];
            #pragma unroll
            for (int i = 0; i < 4; i++)
                #pragma unroll
                for (int j = 0; j < 4; j++)
                    acc[i][j] = fmaf(a[i], b[j], acc[i][j]);
        }
        __syncthreads();
    }

    #pragma unroll
    for (int i = 0; i < 4; i++)
        *(float4*)(g_P + (size_t)(m0 + ty*4 + i) * INCH + n0 + tx*4) =
            make_float4(acc[i][0], acc[i][1], acc[i][2], acc[i][3]);
}

// ============================================================
// Kernel 9: GATHER-RECON — x_recon[t] = P_c[ic] + P_p[ip] + P_t[it] + br
// 2 tokens per 256-thread block; float4 lanes. P is L2-resident (5 MB).
// ============================================================
__global__ __launch_bounds__(256) void gather_recon_kernel(
    const float* __restrict__ br, float* __restrict__ out)
{
    __shared__ float sbr[INCH];
    const int tid = threadIdx.x;
    #pragma unroll
    for (int q = 0; q < 2; q++) sbr[tid + q*256] = br[tid + q*256];
    __syncthreads();

    const int slot = tid >> 7;                  // 0..1
    const int c4   = (tid & 127) * 4;           // 0..508
    const int tok  = blockIdx.x * 2 + slot;

    const int ic = g_idx[tok];
    const int ip = g_idx[NTOK + tok];
    const int it = g_idx[2*NTOK + tok];

    float4 pc = *(const float4*)(g_P + (size_t)ic * INCH + c4);
    float4 pp = *(const float4*)(g_P + (size_t)(VC + ip) * INCH + c4);
    float4 pt = *(const float4*)(g_P + (size_t)(VC + VP + it) * INCH + c4);

    float4 r;
    r.x = pc.x + pp.x + pt.x + sbr[c4+0];
    r.y = pc.y + pp.y + pt.y + sbr[c4+1];
    r.z = pc.z + pp.z + pt.z + sbr[c4+2];
    r.w = pc.w + pp.w + pt.w + sbr[c4+3];
    *(float4*)(out + (size_t)tok * INCH + c4) = r;
}

// ============================================================
extern "C" void kernel_launch(void* const* d_in, const int* in_sizes, int n_in,
                              void* d_out, int out_size)
{
    (void)in_sizes; (void)n_in; (void)out_size;
    const float* x   = (const float*)d_in[0];
    const float* Wc  = (const float*)d_in[1];
    const float* bc  = (const float*)d_in[2];
    const float* Wp  = (const float*)d_in[3];
    const float* bp  = (const float*)d_in[4];
    const float* Wt  = (const float*)d_in[5];
    const float* bt  = (const float*)d_in[6];
    const float* cbc = (const float*)d_in[7];
    const float* cbp = (const float*)d_in[8];
    const float* cbt = (const float*)d_in[9];
    const float* Wr  = (const float*)d_in[10];
    const float* br  = (const float*)d_in[11];
    float* out = (float*)d_out;

    const int SMEM_DYN1 = 2 * (256 * PAD) * 4;   // 40960
    cudaFuncSetAttribute(screen_mma, cudaFuncAttributeMaxDynamicSharedMemorySize, SMEM_DYN1);

    pproj_kernel<<<dim3(VTOT/64, INCH/64), 256>>>(cbc, cbp, cbt, Wr);
    gemm_z_kernel<<<dim3(6, NTOK/128), 256>>>(x, Wc, Wp, Wt, bc, bp, bt);
    zz_kernel<<<(3*NTOK)/8, 256>>>();
    cc_kernel<<<VTOT/8, 256>>>(cbc, cbp, cbt);
    screen_mma<<<dim3(VC/128, NTOK/128), 256, SMEM_DYN1>>>(cbc, 0, 0, 1024, 0);
    screen_mma<<<dim3(VP/128, NTOK/128), 256, SMEM_DYN1>>>(cbp, 1, VC, 1024, (size_t)NTOK*1024);
    screen_mma<<<dim3(VT/128, NTOK/128), 256, SMEM_DYN1>>>(cbt, 2, VC+VP, 512, (size_t)2*NTOK*1024);
    rescore_kernel<<<dim3(NTOK/8, 3), 256>>>(cbc, cbp, cbt, out);
    merge_kernel<<<dim3(NTOK/64, 3), 256>>>(cbc, cbp, cbt, out);
    loss_kernel<<<1, 256>>>(out);
    gather_recon_kernel<<<NTOK/2, 256>>>(br, out);
}